// round 14
// baseline (speedup 1.0000x reference)
#include <cuda_runtime.h>
#include <cuda_fp16.h>
#include <cstdint>
#include <math.h>

// ---------------- problem constants ----------------
#define Bb 2
#define Rr 4096
#define Ss 48
#define NRAY   (Bb*Rr)        // 8192
#define NSAMP  (NRAY*Ss)      // 393216
#define NG16   (NSAMP/16)     // 24576

#define RAY_START 2.25f
#define STEPF 0.0223404255319148936f  // (3.3-2.25)/47

#define OUT_RGB   0
#define OUT_DEPTH 262144
#define OUT_WT    270336
#define OUT_XYZ   278528

#define MODEL_BLOCKS 296
#define MODEL_WARPS  (MODEL_BLOCKS*16)   // 4736

// ---------------- scratch ----------------
__device__ __half g_planes_h[(size_t)Bb*3*256*256*64];
__device__ float g_depth_c[NSAMP];
__device__ float g_depth_f[NSAMP];
__device__ float g_col_c[(size_t)NSAMP*32];
__device__ float g_col_f[(size_t)NSAMP*32];
__device__ float g_sig_c[NSAMP];
__device__ float g_sig_f[NSAMP];
__device__ int   g_dmin_bits;
__device__ int   g_dmax_bits;
__device__ unsigned int g_ctr0;
__device__ unsigned int g_ctr1;

// ---------------- math helpers ----------------
__device__ __forceinline__ float softplusf(float x) {
    return fmaxf(x, 0.0f) + log1pf(expf(-fabsf(x)));
}
__device__ __forceinline__ float softplus_fast(float x) {
    return fmaxf(x, 0.0f) + __logf(1.0f + __expf(-fabsf(x)));
}
__device__ __forceinline__ float sigmoid_fast(float x) {
    return __fdividef(1.0f, 1.0f + __expf(-x));
}

__device__ __forceinline__ uint32_t smaddr(const void* p) {
    return (uint32_t)__cvta_generic_to_shared(p);
}
__device__ __forceinline__ void ldsm_x4(uint32_t& r0, uint32_t& r1, uint32_t& r2, uint32_t& r3, uint32_t a) {
    asm volatile("ldmatrix.sync.aligned.m8n8.x4.shared.b16 {%0,%1,%2,%3}, [%4];"
                 : "=r"(r0), "=r"(r1), "=r"(r2), "=r"(r3) : "r"(a));
}
__device__ __forceinline__ void ldsm_x2(uint32_t& r0, uint32_t& r1, uint32_t a) {
    asm volatile("ldmatrix.sync.aligned.m8n8.x2.shared.b16 {%0,%1}, [%2];"
                 : "=r"(r0), "=r"(r1) : "r"(a));
}
__device__ __forceinline__ void mma_f16(float& d0, float& d1, float& d2, float& d3,
                                        uint32_t a0, uint32_t a1, uint32_t a2, uint32_t a3,
                                        uint32_t b0, uint32_t b1) {
    asm volatile(
        "mma.sync.aligned.m16n8k16.row.col.f32.f16.f16.f32 "
        "{%0,%1,%2,%3}, {%4,%5,%6,%7}, {%8,%9}, {%0,%1,%2,%3};"
        : "+f"(d0), "+f"(d1), "+f"(d2), "+f"(d3)
        : "r"(a0), "r"(a1), "r"(a2), "r"(a3), "r"(b0), "r"(b1));
}

// ---------------- Threefry-2x32 (JAX, partitionable variant) ----------------
__device__ __forceinline__ uint32_t rotl32(uint32_t x, int r) {
    return (x << r) | (x >> (32 - r));
}
__device__ __forceinline__ void tf2x32(uint32_t k0, uint32_t k1,
                                       uint32_t x0, uint32_t x1,
                                       uint32_t& o0, uint32_t& o1) {
    uint32_t ks2 = k0 ^ k1 ^ 0x1BD11BDAu;
    x0 += k0; x1 += k1;
#define TFR(r) { x0 += x1; x1 = rotl32(x1, r); x1 ^= x0; }
    TFR(13) TFR(15) TFR(26) TFR(6)  x0 += k1;  x1 += ks2 + 1u;
    TFR(17) TFR(29) TFR(16) TFR(24) x0 += ks2; x1 += k0 + 2u;
    TFR(13) TFR(15) TFR(26) TFR(6)  x0 += k0;  x1 += k1 + 3u;
    TFR(17) TFR(29) TFR(16) TFR(24) x0 += k1;  x1 += ks2 + 4u;
    TFR(13) TFR(15) TFR(26) TFR(6)  x0 += ks2; x1 += k0 + 5u;
#undef TFR
    o0 = x0; o1 = x1;
}
__device__ __forceinline__ void derive_key(uint32_t idx, uint32_t& ka, uint32_t& kb) {
    tf2x32(0u, 42u, 0u, idx, ka, kb);
}
__device__ __forceinline__ float tf_uniform(uint32_t ka, uint32_t kb, uint32_t i) {
    uint32_t o0, o1;
    tf2x32(ka, kb, 0u, i, o0, o1);
    uint32_t bits = o0 ^ o1;
    float f = __uint_as_float((bits >> 9) | 0x3f800000u) - 1.0f;
    return fmaxf(f, 0.0f);
}

// ---------------- kernel 1: transpose planes to channel-last fp16 (+ init scalars) ----------------
__global__ void k_transpose(const float* __restrict__ front, const float* __restrict__ back) {
    __shared__ float tf[32][33];
    __shared__ float tb[32][33];
    if (blockIdx.x == 0 && blockIdx.y == 0 && blockIdx.z == 0 &&
        threadIdx.x == 0 && threadIdx.y == 0) {
        g_dmin_bits = 0x7f800000;
        g_dmax_bits = 0x00000000;
        g_ctr0 = MODEL_WARPS;
    }
    int bp = blockIdx.z;
    int y  = blockIdx.y;
    int x0 = blockIdx.x * 32;
    int tx = threadIdx.x, ty = threadIdx.y;
    __half2* out = (__half2*)g_planes_h;
#pragma unroll
    for (int i = 0; i < 4; i++) {
        int c = ty + i * 8;
        size_t src = ((size_t)(bp * 32 + c) * 65536) + (size_t)y * 256 + x0 + tx;
        tf[c][tx] = front[src];
        tb[c][tx] = back[src];
    }
    __syncthreads();
#pragma unroll
    for (int i = 0; i < 4; i++) {
        int xx = ty + i * 8;
        out[(((size_t)bp * 65536) + (size_t)y * 256 + x0 + xx) * 32 + tx] =
            __floats2half2_rn(tf[tx][xx], tb[tx][xx]);
    }
}

// ---------------- kernel 2: model, warp per 16-sample group, fp16 mma MLP ----------------
#define SM_W1H  0
#define SM_W2H  3328
#define SM_B1   4768
#define SM_B2   4832
#define SM_WSIG 4872
#define SM_XB   4968
#define SM_HB   18280
#define SM_TOTAL_BYTES (27496*4)

extern __shared__ __align__(16) float smem[];

struct Axis { float w0, w1; int i0, i1; bool ok; };
__device__ __forceinline__ Axis axis_prep(float g) {
    Axis a;
    float x = (g + 1.0f) * 128.0f - 0.5f;
    float x0f = floorf(x);
    int x0 = (int)x0f;
    float w = x - x0f;
    bool v0 = (x0 >= 0) & (x0 < 256);
    bool v1 = (x0 >= -1) & (x0 < 255);
    a.w0 = v0 ? 1.0f - w : 0.0f;
    a.w1 = v1 ? w : 0.0f;
    a.i0 = min(max(x0, 0), 255);
    a.i1 = min(max(x0 + 1, 0), 255);
    a.ok = (x0 >= -1) & (x0 <= 255);
    return a;
}

__global__ void __launch_bounds__(512, 2) k_model(
    const float* __restrict__ ro, const float* __restrict__ rd,
    const float* __restrict__ weight,
    const float* __restrict__ w1, const float* __restrict__ b1,
    const float* __restrict__ w2, const float* __restrict__ b2,
    int fine_pass)
{
    __half* w1h = (__half*)(smem + SM_W1H);
    __half* w2h = (__half*)(smem + SM_W2H);
    float* b1s  = smem + SM_B1;
    float* b2s  = smem + SM_B2;
    float* wsig = smem + SM_WSIG;

    int tid = threadIdx.x;
    for (int i = tid; i < 96 * 64; i += 512) {
        int k = i >> 6, n = i & 63;
        w1h[n * 104 + k] = __float2half(w1[i]);
    }
    for (int i = tid; i < 64 * 40; i += 512) {
        int k = i / 40, n = i % 40;
        w2h[n * 72 + k] = (n < 33) ? __float2half(w2[k * 33 + n]) : __half(0.0f);
    }
    if (tid < 64) b1s[tid] = b1[tid];
    if (tid < 40) b2s[tid] = (tid < 33) ? b2[tid] : 0.0f;
    if (tid < 96) wsig[tid] = 1.0f / (1.0f + expf(-weight[tid]));
    __syncthreads();

    float* cols = fine_pass ? g_col_f : g_col_c;
    float* sigs = fine_pass ? g_sig_f : g_sig_c;
    unsigned int* ctr = fine_pass ? &g_ctr1 : &g_ctr0;

    int lane = tid & 31, wrp = tid >> 5;
    int tq = lane & 3;
    __half* xh = (__half*)(smem + SM_XB) + wrp * 1664;   // [16][104]
    __half* hh = (__half*)(smem + SM_HB) + wrp * 1152;   // [16][72]
    float*  outf = (float*)xh;                           // reuse as [16][44] float

    uint32_t a_x = smaddr(xh) + (((lane & 15) * 104 + ((lane >> 4) * 8)) * 2);
    uint32_t a_h = smaddr(hh) + (((lane & 15) * 72  + ((lane >> 4) * 8)) * 2);
    uint32_t b_w1 = smaddr(w1h) + (((lane & 7) * 104 + (((lane >> 3) & 1) * 8)) * 2);
    uint32_t b_w2 = smaddr(w2h) + (((lane & 7) * 72  + (((lane >> 3) & 1) * 8)) * 2);

    float wk0 = wsig[lane], wk1 = wsig[32 + lane], wk2 = wsig[64 + lane];

    uint32_t ka0, kb0; derive_key(0u, ka0, kb0);

    int g = blockIdx.x * 16 + wrp;

    while (g < NG16) {
        int smp0 = g * 16;
        int ray = g / 3;
        int b = ray >> 12;
        float ox = 2.0f * ro[ray * 3 + 0], oy = 2.0f * ro[ray * 3 + 1], oz = 2.0f * ro[ray * 3 + 2];
        float dx = 2.0f * rd[ray * 3 + 0], dy = 2.0f * rd[ray * 3 + 1], dz = 2.0f * rd[ray * 3 + 2];
        const __half2* pb0 = (const __half2*)g_planes_h + (size_t)b * 3 * 65536 * 32 + (size_t)lane;
        const __half2* pb1 = pb0 + (size_t)65536 * 32;
        const __half2* pb2 = pb1 + (size_t)65536 * 32;

        int sidx = smp0 + (lane & 15);
        float dval;
        if (!fine_pass) {
            int sloc = (g % 3) * 16 + (lane & 15);
            float u = tf_uniform(ka0, kb0, (uint32_t)sidx);
            float d0 = RAY_START + (float)sloc * STEPF;
            dval = d0 + u * STEPF;
            if (lane < 16) g_depth_c[sidx] = dval;
        } else {
            dval = g_depth_f[sidx];
        }

        int gnext;
        if (lane == 0) gnext = (int)atomicAdd(ctr, 1u);
        gnext = __shfl_sync(0xffffffffu, gnext, 0);

        // ---- phase A: gather 16 samples, lane = channel ----
        // sample-level OOB skip (ax shared by all planes); interior branchless:
        // zero weights from axis_prep make OOB taps exact zeros, and all 12
        // loads issue back-to-back for max memory-level parallelism.
#pragma unroll 4
        for (int s = 0; s < 16; s++) {
            float d = __shfl_sync(0xffffffffu, dval, s);
            float cx = fmaf(d, dx, ox);
            float cy = fmaf(d, dy, oy);
            float cz = fmaf(d, dz, oz);
            float xv0 = 0.0f, xv1 = 0.0f, xv2 = 0.0f;
            Axis ax = axis_prep(cx);
            if (ax.ok) {
                Axis ay = axis_prep(cy);
                Axis az = axis_prep(cz);
                // issue all 12 tap loads first
                float2 p0v00 = __half22float2(pb0[(ay.i0 * 256 + ax.i0) * 32]);
                float2 p0v01 = __half22float2(pb0[(ay.i0 * 256 + ax.i1) * 32]);
                float2 p0v10 = __half22float2(pb0[(ay.i1 * 256 + ax.i0) * 32]);
                float2 p0v11 = __half22float2(pb0[(ay.i1 * 256 + ax.i1) * 32]);
                float2 p1v00 = __half22float2(pb1[(az.i0 * 256 + ax.i0) * 32]);
                float2 p1v01 = __half22float2(pb1[(az.i0 * 256 + ax.i1) * 32]);
                float2 p1v10 = __half22float2(pb1[(az.i1 * 256 + ax.i0) * 32]);
                float2 p1v11 = __half22float2(pb1[(az.i1 * 256 + ax.i1) * 32]);
                float2 p2v00 = __half22float2(pb2[(ax.i0 * 256 + az.i0) * 32]);
                float2 p2v01 = __half22float2(pb2[(ax.i0 * 256 + az.i1) * 32]);
                float2 p2v10 = __half22float2(pb2[(ax.i1 * 256 + az.i0) * 32]);
                float2 p2v11 = __half22float2(pb2[(ax.i1 * 256 + az.i1) * 32]);
                {   // plane 0: (ax, ay)
                    float w00 = ax.w0 * ay.w0, w01 = ax.w1 * ay.w0;
                    float w10 = ax.w0 * ay.w1, w11 = ax.w1 * ay.w1;
                    float aF = fmaf(w11, p0v11.x, fmaf(w10, p0v10.x, fmaf(w01, p0v01.x, w00 * p0v00.x)));
                    float aB = fmaf(w11, p0v11.y, fmaf(w10, p0v10.y, fmaf(w01, p0v01.y, w00 * p0v00.y)));
                    xv0 = wk0 * aF + (1.0f - wk0) * aB;
                }
                {   // plane 1: (ax, az)
                    float w00 = ax.w0 * az.w0, w01 = ax.w1 * az.w0;
                    float w10 = ax.w0 * az.w1, w11 = ax.w1 * az.w1;
                    float aF = fmaf(w11, p1v11.x, fmaf(w10, p1v10.x, fmaf(w01, p1v01.x, w00 * p1v00.x)));
                    float aB = fmaf(w11, p1v11.y, fmaf(w10, p1v10.y, fmaf(w01, p1v01.y, w00 * p1v00.y)));
                    xv1 = wk1 * aF + (1.0f - wk1) * aB;
                }
                {   // plane 2: (az, ax)
                    float w00 = az.w0 * ax.w0, w01 = az.w1 * ax.w0;
                    float w10 = az.w0 * ax.w1, w11 = az.w1 * ax.w1;
                    float aF = fmaf(w11, p2v11.x, fmaf(w10, p2v10.x, fmaf(w01, p2v01.x, w00 * p2v00.x)));
                    float aB = fmaf(w11, p2v11.y, fmaf(w10, p2v10.y, fmaf(w01, p2v01.y, w00 * p2v00.y)));
                    xv2 = wk2 * aF + (1.0f - wk2) * aB;
                }
            }
            xh[s * 104 + lane]      = __float2half(xv0);
            xh[s * 104 + 32 + lane] = __float2half(xv1);
            xh[s * 104 + 64 + lane] = __float2half(xv2);
        }
        __syncwarp();

        // ---- layer1: [16x96] @ [96x64], fp16 mma, n split in halves ----
#pragma unroll
        for (int hn = 0; hn < 2; hn++) {
            float d1[4][4];
#pragma unroll
            for (int nt2 = 0; nt2 < 4; nt2++) {
                int nt = hn * 4 + nt2;
                float bl = b1s[nt * 8 + 2 * tq], bh = b1s[nt * 8 + 2 * tq + 1];
                d1[nt2][0] = bl; d1[nt2][1] = bh; d1[nt2][2] = bl; d1[nt2][3] = bh;
            }
#pragma unroll
            for (int kt = 0; kt < 6; kt++) {
                uint32_t a0, a1, a2, a3;
                ldsm_x4(a0, a1, a2, a3, a_x + kt * 32);
#pragma unroll
                for (int nt2 = 0; nt2 < 4; nt2++) {
                    int nt = hn * 4 + nt2;
                    uint32_t bv0, bv1;
                    ldsm_x2(bv0, bv1, b_w1 + nt * 1664 + kt * 32);
                    mma_f16(d1[nt2][0], d1[nt2][1], d1[nt2][2], d1[nt2][3], a0, a1, a2, a3, bv0, bv1);
                }
            }
            int gq = lane >> 2;
#pragma unroll
            for (int nt2 = 0; nt2 < 4; nt2++) {
                int nt = hn * 4 + nt2;
                *(__half2*)(hh + gq * 72 + nt * 8 + 2 * tq) =
                    __floats2half2_rn(softplus_fast(d1[nt2][0]), softplus_fast(d1[nt2][1]));
                *(__half2*)(hh + (gq + 8) * 72 + nt * 8 + 2 * tq) =
                    __floats2half2_rn(softplus_fast(d1[nt2][2]), softplus_fast(d1[nt2][3]));
            }
        }
        __syncwarp();

        // ---- layer2: [16x64] @ [64x40] ----
        float d2[5][4];
#pragma unroll
        for (int nt = 0; nt < 5; nt++) {
            float bl = b2s[nt * 8 + 2 * tq], bh = b2s[nt * 8 + 2 * tq + 1];
            d2[nt][0] = bl; d2[nt][1] = bh; d2[nt][2] = bl; d2[nt][3] = bh;
        }
#pragma unroll
        for (int kt = 0; kt < 4; kt++) {
            uint32_t a0, a1, a2, a3;
            ldsm_x4(a0, a1, a2, a3, a_h + kt * 32);
#pragma unroll
            for (int nt = 0; nt < 5; nt++) {
                uint32_t bv0, bv1;
                ldsm_x2(bv0, bv1, b_w2 + nt * 1152 + kt * 32);
                mma_f16(d2[nt][0], d2[nt][1], d2[nt][2], d2[nt][3], a0, a1, a2, a3, bv0, bv1);
            }
        }
        __syncwarp();
        {
            int gq = lane >> 2;
#pragma unroll
            for (int nt = 0; nt < 5; nt++) {
                *(float2*)(outf + gq * 44 + nt * 8 + 2 * tq)       = make_float2(d2[nt][0], d2[nt][1]);
                *(float2*)(outf + (gq + 8) * 44 + nt * 8 + 2 * tq) = make_float2(d2[nt][2], d2[nt][3]);
            }
        }
        __syncwarp();

#pragma unroll 4
        for (int s = 0; s < 16; s++) {
            float v = outf[s * 44 + 1 + lane];
            cols[(size_t)(smp0 + s) * 32 + lane] = sigmoid_fast(v) * 1.002f - 0.001f;
        }
        if (lane < 16) sigs[smp0 + lane] = outf[lane * 44];
        __syncwarp();

        g = gnext;
    }
}

// ---------------- kernel 3: fused coarse weights + importance sampling, warp per ray ----------------
#define KF_W 8
__global__ void __launch_bounds__(KF_W*32) k_fine() {
    __shared__ float zsh[KF_W][49];
    __shared__ float ssh[KF_W][49];
    __shared__ float wsh[KF_W][48];
    __shared__ float zmsh[KF_W][48];
    __shared__ float cdfsh[KF_W][47];
    __shared__ float bmn[KF_W], bmx[KF_W];
    if (blockIdx.x == 0 && threadIdx.x == 0) g_ctr1 = MODEL_WARPS;
    int lane = threadIdx.x & 31, wrp = threadIdx.x >> 5;
    int ray = blockIdx.x * KF_W + wrp;
    float* z   = zsh[wrp];
    float* sg  = ssh[wrp];
    float* w   = wsh[wrp];
    float* zm  = zmsh[wrp];
    float* cdf = cdfsh[wrp];

    for (int i = lane; i < 48; i += 32) {
        z[i]  = g_depth_c[ray * 48 + i];
        sg[i] = g_sig_c[ray * 48 + i];
    }
    __syncwarp();

    float a0, t0, a1 = 0.0f, t1 = 1.0f;
    {
        int i = lane;
        float dens = softplusf(0.5f * (sg[i] + sg[i + 1]) - 1.0f);
        a0 = 1.0f - expf(-dens * (z[i + 1] - z[i]));
        t0 = 1.0f - a0 + 1e-10f;
        zm[i] = 0.5f * (z[i] + z[i + 1]);
    }
    if (lane < 15) {
        int i = 32 + lane;
        float dens = softplusf(0.5f * (sg[i] + sg[i + 1]) - 1.0f);
        a1 = 1.0f - expf(-dens * (z[i + 1] - z[i]));
        t1 = 1.0f - a1 + 1e-10f;
        zm[i] = 0.5f * (z[i] + z[i + 1]);
    }
    float p0 = t0;
#pragma unroll
    for (int off = 1; off < 32; off <<= 1) {
        float v = __shfl_up_sync(0xffffffffu, p0, off);
        if (lane >= off) p0 *= v;
    }
    float tot0 = __shfl_sync(0xffffffffu, p0, 31);
    float p0prev = __shfl_up_sync(0xffffffffu, p0, 1);
    float P0 = (lane == 0) ? 1.0f : p0prev;
    float p1 = t1;
#pragma unroll
    for (int off = 1; off < 32; off <<= 1) {
        float v = __shfl_up_sync(0xffffffffu, p1, off);
        if (lane >= off) p1 *= v;
    }
    float p1prev = __shfl_up_sync(0xffffffffu, p1, 1);
    float P1 = tot0 * ((lane == 0) ? 1.0f : p1prev);

    w[lane] = a0 * P0;
    if (lane < 15) w[32 + lane] = a1 * P1;
    __syncwarp();

    if (lane == 0) { bmn[wrp] = z[0]; bmx[wrp] = z[47]; }
    __syncthreads();
    if (threadIdx.x == 0) {
        float mn = bmn[0], mx = bmx[0];
#pragma unroll
        for (int i = 1; i < KF_W; i++) { mn = fminf(mn, bmn[i]); mx = fmaxf(mx, bmx[i]); }
        atomicMin(&g_dmin_bits, __float_as_int(mn));
        atomicMax(&g_dmax_bits, __float_as_int(mx));
    }

    float s0 = 0.0f, s1 = 0.0f;
    {
        int j = lane;
        if (j < 45)
            s0 = 0.5f * (fmaxf(w[j], w[j + 1]) + fmaxf(w[j + 1], w[j + 2])) + 0.01f + 1e-5f;
    }
    if (lane < 13) {
        int j = 32 + lane;
        s1 = 0.5f * (fmaxf(w[j], w[j + 1]) + fmaxf(w[j + 1], w[j + 2])) + 0.01f + 1e-5f;
    }
    float q0 = s0;
#pragma unroll
    for (int off = 1; off < 32; off <<= 1) {
        float v = __shfl_up_sync(0xffffffffu, q0, off);
        if (lane >= off) q0 += v;
    }
    float tot0s = __shfl_sync(0xffffffffu, q0, 31);
    float q1 = s1;
#pragma unroll
    for (int off = 1; off < 32; off <<= 1) {
        float v = __shfl_up_sync(0xffffffffu, q1, off);
        if (lane >= off) q1 += v;
    }
    float sum = tot0s + __shfl_sync(0xffffffffu, q1, 31);
    if (lane == 0) cdf[0] = 0.0f;
    if (lane < 45) cdf[lane + 1] = q0 / sum;
    if (lane < 13) cdf[33 + lane] = (tot0s + q1) / sum;
    __syncwarp();

    uint32_t ka, kb; derive_key(1u, ka, kb);
#pragma unroll
    for (int half = 0; half < 2; half++) {
        int j = half * 32 + lane;
        if (j < 48) {
            float u = tf_uniform(ka, kb, (uint32_t)(ray * 48 + j));
            int pos = 0;
#pragma unroll
            for (int step = 32; step; step >>= 1) {
                int np = pos + step;
                if (np <= 46 && cdf[np - 1] <= u) pos = np;
            }
            int ind = pos;
            int below = ind - 1; if (below < 0) below = 0;
            int above = ind;     if (above > 45) above = 45;
            float c0 = cdf[below], c1 = cdf[above];
            float b0 = zm[below],  b1v = zm[above];
            float denom = c1 - c0;
            if (denom < 1e-5f) denom = 1.0f;
            g_depth_f[ray * 48 + j] = b0 + (u - c0) / denom * (b1v - b0);
        }
    }
}

// ---------------- kernel 4: unify + final march, warp per ray, parallel scan ----------------
#define KL_W 8
__global__ void __launch_bounds__(KL_W*32) k_final(
    const float* __restrict__ ro, const float* __restrict__ rd,
    float* __restrict__ out)
{
    __shared__ __align__(16) float sd[KL_W][96];
    __shared__ __align__(16) float ssg[KL_W][96];
    __shared__ __align__(16) float wbuf[KL_W][96];
    __shared__ __align__(16) int   sidx[KL_W][96];
    int lane = threadIdx.x & 31, wrp = threadIdx.x >> 5;
    int ray = blockIdx.x * KL_W + wrp;

    for (int i = lane; i < 48; i += 32) {
        sd[wrp][i]       = g_depth_c[ray * 48 + i];
        sd[wrp][48 + i]  = g_depth_f[ray * 48 + i];
        ssg[wrp][i]      = g_sig_c[ray * 48 + i];
        ssg[wrp][48 + i] = g_sig_f[ray * 48 + i];
    }
    __syncwarp();
#pragma unroll
    for (int t = 0; t < 3; t++) {
        int e = lane + t * 32;
        float de = sd[wrp][e];
        int rank = 0;
        for (int j = 0; j < 96; j++) {
            float dj = sd[wrp][j];
            rank += (dj < de || (dj == de && j < e)) ? 1 : 0;
        }
        sidx[wrp][rank] = e;
    }
    __syncwarp();

    float av[3], tv[3], dm[3];
#pragma unroll
    for (int c = 0; c < 3; c++) {
        int k = c * 32 + lane;
        av[c] = 0.0f; tv[c] = 1.0f; dm[c] = 0.0f;
        if (k < 95) {
            int i0 = sidx[wrp][k], i1 = sidx[wrp][k + 1];
            float d0 = sd[wrp][i0], d1 = sd[wrp][i1];
            float s0 = ssg[wrp][i0], s1 = ssg[wrp][i1];
            float dens = softplus_fast(0.5f * (s0 + s1) - 1.0f);
            float alpha = 1.0f - __expf(-dens * (d1 - d0));
            av[c] = alpha;
            tv[c] = 1.0f - alpha + 1e-10f;
            dm[c] = 0.5f * (d0 + d1);
        }
    }
    float carry = 1.0f;
    float accW = 0.0f, accWD = 0.0f;
#pragma unroll
    for (int c = 0; c < 3; c++) {
        float p = tv[c];
#pragma unroll
        for (int off = 1; off < 32; off <<= 1) {
            float v = __shfl_up_sync(0xffffffffu, p, off);
            if (lane >= off) p *= v;
        }
        float pprev = __shfl_up_sync(0xffffffffu, p, 1);
        float P = carry * ((lane == 0) ? 1.0f : pprev);
        float wk = av[c] * P;
        int k = c * 32 + lane;
        wbuf[wrp][k] = (k < 95) ? wk : 0.0f;
        if (k < 95) { accW += wk; accWD += wk * dm[c]; }
        carry *= __shfl_sync(0xffffffffu, p, 31);
    }
    if (lane == 31) wbuf[wrp][95] = 0.0f;
#pragma unroll
    for (int off = 16; off; off >>= 1) {
        accW  += __shfl_xor_sync(0xffffffffu, accW, off);
        accWD += __shfl_xor_sync(0xffffffffu, accWD, off);
    }
    __syncwarp();

    const float* colc = g_col_c + (size_t)ray * 48 * 32 + lane;
    const float* colf = g_col_f + (size_t)ray * 48 * 32 + lane;
    float accC = 0.0f;
#pragma unroll 8
    for (int j = 0; j < 96; j++) {
        float wj  = (j < 95) ? wbuf[wrp][j] : 0.0f;
        float wjm = (j > 0)  ? wbuf[wrp][j - 1] : 0.0f;
        float coef = 0.5f * (wj + wjm);
        int i = sidx[wrp][j];
        const float* cb = (i < 48) ? colc : colf;
        float cc = cb[(size_t)(i < 48 ? i : i - 48) * 32];
        accC = fmaf(coef, cc, accC);
    }

    out[OUT_RGB + (size_t)ray * 32 + lane] = accC * 2.0f - 1.0f;
    if (lane == 0) {
        float wt = accW;
        float dep = accWD / wt;
        if (isnan(dep)) dep = __int_as_float(0x7f800000);
        float dmin = __int_as_float(g_dmin_bits);
        float dmax = __int_as_float(g_dmax_bits);
        dep = fminf(fmaxf(dep, dmin), dmax);
        out[OUT_DEPTH + ray] = dep;
        out[OUT_WT + ray] = wt;
    }
    if (lane < 3) {
        float o_ = ro[ray * 3 + lane], d_ = rd[ray * 3 + lane];
        out[OUT_XYZ + (size_t)ray * 3 + lane] = 2.0f * (o_ * accW + d_ * accWD) - 1.0f;
    }
}

// ---------------- launcher ----------------
extern "C" void kernel_launch(void* const* d_in, const int* in_sizes, int n_in,
                              void* d_out, int out_size) {
    const float* front  = (const float*)d_in[0];
    const float* back   = (const float*)d_in[1];
    const float* ro     = (const float*)d_in[2];
    const float* rd     = (const float*)d_in[3];
    const float* weight = (const float*)d_in[4];
    const float* w1     = (const float*)d_in[5];
    const float* b1     = (const float*)d_in[6];
    const float* w2     = (const float*)d_in[7];
    const float* b2     = (const float*)d_in[8];
    float* out = (float*)d_out;

    cudaFuncSetAttribute(k_model, cudaFuncAttributeMaxDynamicSharedMemorySize, SM_TOTAL_BYTES);

    k_transpose<<<dim3(8, 256, 6), dim3(32, 8)>>>(front, back);
    k_model<<<MODEL_BLOCKS, 512, SM_TOTAL_BYTES>>>(ro, rd, weight, w1, b1, w2, b2, 0);
    k_fine<<<NRAY / KF_W, KF_W * 32>>>();
    k_model<<<MODEL_BLOCKS, 512, SM_TOTAL_BYTES>>>(ro, rd, weight, w1, b1, w2, b2, 1);
    k_final<<<NRAY / KL_W, KL_W * 32>>>(ro, rd, out);
    (void)in_sizes; (void)n_in; (void)out_size;
}

// round 15
// speedup vs baseline: 1.0413x; 1.0413x over previous
#include <cuda_runtime.h>
#include <cuda_fp16.h>
#include <cstdint>
#include <math.h>

// ---------------- problem constants ----------------
#define Bb 2
#define Rr 4096
#define Ss 48
#define NRAY   (Bb*Rr)        // 8192
#define NSAMP  (NRAY*Ss)      // 393216
#define NG16   (NSAMP/16)     // 24576

#define RAY_START 2.25f
#define STEPF 0.0223404255319148936f  // (3.3-2.25)/47

#define OUT_RGB   0
#define OUT_DEPTH 262144
#define OUT_WT    270336
#define OUT_XYZ   278528

#define MODEL_BLOCKS 296
#define MODEL_WARPS  (MODEL_BLOCKS*16)   // 4736

// ---------------- scratch ----------------
__device__ __half g_planes_h[(size_t)Bb*3*256*256*64];
__device__ float g_depth_c[NSAMP];
__device__ float g_depth_f[NSAMP];
__device__ float g_col_c[(size_t)NSAMP*32];
__device__ float g_col_f[(size_t)NSAMP*32];
__device__ float g_sig_c[NSAMP];
__device__ float g_sig_f[NSAMP];
__device__ int   g_dmin_bits;
__device__ int   g_dmax_bits;
__device__ unsigned int g_ctr0;
__device__ unsigned int g_ctr1;

// ---------------- math helpers ----------------
__device__ __forceinline__ float softplusf(float x) {
    return fmaxf(x, 0.0f) + log1pf(expf(-fabsf(x)));
}
__device__ __forceinline__ float softplus_fast(float x) {
    return fmaxf(x, 0.0f) + __logf(1.0f + __expf(-fabsf(x)));
}
__device__ __forceinline__ float sigmoid_fast(float x) {
    return __fdividef(1.0f, 1.0f + __expf(-x));
}

__device__ __forceinline__ uint32_t smaddr(const void* p) {
    return (uint32_t)__cvta_generic_to_shared(p);
}
__device__ __forceinline__ void ldsm_x4(uint32_t& r0, uint32_t& r1, uint32_t& r2, uint32_t& r3, uint32_t a) {
    asm volatile("ldmatrix.sync.aligned.m8n8.x4.shared.b16 {%0,%1,%2,%3}, [%4];"
                 : "=r"(r0), "=r"(r1), "=r"(r2), "=r"(r3) : "r"(a));
}
__device__ __forceinline__ void ldsm_x2(uint32_t& r0, uint32_t& r1, uint32_t a) {
    asm volatile("ldmatrix.sync.aligned.m8n8.x2.shared.b16 {%0,%1}, [%2];"
                 : "=r"(r0), "=r"(r1) : "r"(a));
}
__device__ __forceinline__ void mma_f16(float& d0, float& d1, float& d2, float& d3,
                                        uint32_t a0, uint32_t a1, uint32_t a2, uint32_t a3,
                                        uint32_t b0, uint32_t b1) {
    asm volatile(
        "mma.sync.aligned.m16n8k16.row.col.f32.f16.f16.f32 "
        "{%0,%1,%2,%3}, {%4,%5,%6,%7}, {%8,%9}, {%0,%1,%2,%3};"
        : "+f"(d0), "+f"(d1), "+f"(d2), "+f"(d3)
        : "r"(a0), "r"(a1), "r"(a2), "r"(a3), "r"(b0), "r"(b1));
}

// ---------------- Threefry-2x32 (JAX, partitionable variant) ----------------
__device__ __forceinline__ uint32_t rotl32(uint32_t x, int r) {
    return (x << r) | (x >> (32 - r));
}
__device__ __forceinline__ void tf2x32(uint32_t k0, uint32_t k1,
                                       uint32_t x0, uint32_t x1,
                                       uint32_t& o0, uint32_t& o1) {
    uint32_t ks2 = k0 ^ k1 ^ 0x1BD11BDAu;
    x0 += k0; x1 += k1;
#define TFR(r) { x0 += x1; x1 = rotl32(x1, r); x1 ^= x0; }
    TFR(13) TFR(15) TFR(26) TFR(6)  x0 += k1;  x1 += ks2 + 1u;
    TFR(17) TFR(29) TFR(16) TFR(24) x0 += ks2; x1 += k0 + 2u;
    TFR(13) TFR(15) TFR(26) TFR(6)  x0 += k0;  x1 += k1 + 3u;
    TFR(17) TFR(29) TFR(16) TFR(24) x0 += k1;  x1 += ks2 + 4u;
    TFR(13) TFR(15) TFR(26) TFR(6)  x0 += ks2; x1 += k0 + 5u;
#undef TFR
    o0 = x0; o1 = x1;
}
__device__ __forceinline__ void derive_key(uint32_t idx, uint32_t& ka, uint32_t& kb) {
    tf2x32(0u, 42u, 0u, idx, ka, kb);
}
__device__ __forceinline__ float tf_uniform(uint32_t ka, uint32_t kb, uint32_t i) {
    uint32_t o0, o1;
    tf2x32(ka, kb, 0u, i, o0, o1);
    uint32_t bits = o0 ^ o1;
    float f = __uint_as_float((bits >> 9) | 0x3f800000u) - 1.0f;
    return fmaxf(f, 0.0f);
}

// ---------------- kernel 1: transpose planes to channel-last fp16 (+ init scalars) ----------------
__global__ void k_transpose(const float* __restrict__ front, const float* __restrict__ back) {
    __shared__ float tf[32][33];
    __shared__ float tb[32][33];
    if (blockIdx.x == 0 && blockIdx.y == 0 && blockIdx.z == 0 &&
        threadIdx.x == 0 && threadIdx.y == 0) {
        g_dmin_bits = 0x7f800000;
        g_dmax_bits = 0x00000000;
        g_ctr0 = MODEL_WARPS;
    }
    int bp = blockIdx.z;
    int y  = blockIdx.y;
    int x0 = blockIdx.x * 32;
    int tx = threadIdx.x, ty = threadIdx.y;
    __half2* out = (__half2*)g_planes_h;
#pragma unroll
    for (int i = 0; i < 4; i++) {
        int c = ty + i * 8;
        size_t src = ((size_t)(bp * 32 + c) * 65536) + (size_t)y * 256 + x0 + tx;
        tf[c][tx] = front[src];
        tb[c][tx] = back[src];
    }
    __syncthreads();
#pragma unroll
    for (int i = 0; i < 4; i++) {
        int xx = ty + i * 8;
        out[(((size_t)bp * 65536) + (size_t)y * 256 + x0 + xx) * 32 + tx] =
            __floats2half2_rn(tf[tx][xx], tb[tx][xx]);
    }
}

// ---------------- kernel 2: model, warp per 16-sample group, fp16 mma MLP ----------------
#define SM_W1H  0
#define SM_W2H  3328
#define SM_B1   4768
#define SM_B2   4832
#define SM_WSIG 4872
#define SM_XB   4968
#define SM_HB   18280
#define SM_TOTAL_BYTES (27496*4)

extern __shared__ __align__(16) float smem[];

struct Axis { float w0, w1; int i0, i1; bool ok; };
__device__ __forceinline__ Axis axis_prep(float g) {
    Axis a;
    float x = (g + 1.0f) * 128.0f - 0.5f;
    float x0f = floorf(x);
    int x0 = (int)x0f;
    float w = x - x0f;
    bool v0 = (x0 >= 0) & (x0 < 256);
    bool v1 = (x0 >= -1) & (x0 < 255);
    a.w0 = v0 ? 1.0f - w : 0.0f;
    a.w1 = v1 ? w : 0.0f;
    a.i0 = min(max(x0, 0), 255);
    a.i1 = min(max(x0 + 1, 0), 255);
    a.ok = (x0 >= -1) & (x0 <= 255);
    return a;
}

__global__ void __launch_bounds__(512, 2) k_model(
    const float* __restrict__ ro, const float* __restrict__ rd,
    const float* __restrict__ weight,
    const float* __restrict__ w1, const float* __restrict__ b1,
    const float* __restrict__ w2, const float* __restrict__ b2,
    int fine_pass)
{
    __half* w1h = (__half*)(smem + SM_W1H);
    __half* w2h = (__half*)(smem + SM_W2H);
    float* b1s  = smem + SM_B1;
    float* b2s  = smem + SM_B2;
    float* wsig = smem + SM_WSIG;

    int tid = threadIdx.x;
    for (int i = tid; i < 96 * 64; i += 512) {
        int k = i >> 6, n = i & 63;
        w1h[n * 104 + k] = __float2half(w1[i]);
    }
    for (int i = tid; i < 64 * 40; i += 512) {
        int k = i / 40, n = i % 40;
        w2h[n * 72 + k] = (n < 33) ? __float2half(w2[k * 33 + n]) : __half(0.0f);
    }
    if (tid < 64) b1s[tid] = b1[tid];
    if (tid < 40) b2s[tid] = (tid < 33) ? b2[tid] : 0.0f;
    if (tid < 96) wsig[tid] = 1.0f / (1.0f + expf(-weight[tid]));
    __syncthreads();

    float* cols = fine_pass ? g_col_f : g_col_c;
    float* sigs = fine_pass ? g_sig_f : g_sig_c;
    unsigned int* ctr = fine_pass ? &g_ctr1 : &g_ctr0;

    int lane = tid & 31, wrp = tid >> 5;
    int tq = lane & 3;
    __half* xh = (__half*)(smem + SM_XB) + wrp * 1664;   // [16][104]
    __half* hh = (__half*)(smem + SM_HB) + wrp * 1152;   // [16][72]
    float*  outf = (float*)xh;                           // reuse as [16][44] float

    uint32_t a_x = smaddr(xh) + (((lane & 15) * 104 + ((lane >> 4) * 8)) * 2);
    uint32_t a_h = smaddr(hh) + (((lane & 15) * 72  + ((lane >> 4) * 8)) * 2);
    uint32_t b_w1 = smaddr(w1h) + (((lane & 7) * 104 + (((lane >> 3) & 1) * 8)) * 2);
    uint32_t b_w2 = smaddr(w2h) + (((lane & 7) * 72  + (((lane >> 3) & 1) * 8)) * 2);

    float wk0 = wsig[lane], wk1 = wsig[32 + lane], wk2 = wsig[64 + lane];

    uint32_t ka0, kb0; derive_key(0u, ka0, kb0);

    int g = blockIdx.x * 16 + wrp;

    while (g < NG16) {
        int smp0 = g * 16;
        int ray = g / 3;
        int b = ray >> 12;
        float ox = 2.0f * ro[ray * 3 + 0], oy = 2.0f * ro[ray * 3 + 1], oz = 2.0f * ro[ray * 3 + 2];
        float dx = 2.0f * rd[ray * 3 + 0], dy = 2.0f * rd[ray * 3 + 1], dz = 2.0f * rd[ray * 3 + 2];
        const __half2* pb0 = (const __half2*)g_planes_h + (size_t)b * 3 * 65536 * 32 + (size_t)lane;
        const __half2* pb1 = pb0 + (size_t)65536 * 32;
        const __half2* pb2 = pb1 + (size_t)65536 * 32;

        int sidx = smp0 + (lane & 15);
        float dval;
        if (!fine_pass) {
            int sloc = (g % 3) * 16 + (lane & 15);
            float u = tf_uniform(ka0, kb0, (uint32_t)sidx);
            float d0 = RAY_START + (float)sloc * STEPF;
            dval = d0 + u * STEPF;
            if (lane < 16) g_depth_c[sidx] = dval;
        } else {
            dval = g_depth_f[sidx];
        }

        int gnext;
        if (lane == 0) gnext = (int)atomicAdd(ctr, 1u);
        gnext = __shfl_sync(0xffffffffu, gnext, 0);

        // ---- phase A: gather 16 samples, lane = channel; OOB skips (warp-uniform) ----
#pragma unroll 4
        for (int s = 0; s < 16; s++) {
            float d = __shfl_sync(0xffffffffu, dval, s);
            float cx = fmaf(d, dx, ox);
            float cy = fmaf(d, dy, oy);
            float cz = fmaf(d, dz, oz);
            float xv0 = 0.0f, xv1 = 0.0f, xv2 = 0.0f;
            Axis ax = axis_prep(cx);
            if (ax.ok) {
                Axis ay = axis_prep(cy);
                Axis az = axis_prep(cz);
                if (ay.ok) {   // plane 0: (ax, ay)
                    float2 v00 = __half22float2(pb0[(ay.i0 * 256 + ax.i0) * 32]);
                    float2 v01 = __half22float2(pb0[(ay.i0 * 256 + ax.i1) * 32]);
                    float2 v10 = __half22float2(pb0[(ay.i1 * 256 + ax.i0) * 32]);
                    float2 v11 = __half22float2(pb0[(ay.i1 * 256 + ax.i1) * 32]);
                    float w00 = ax.w0 * ay.w0, w01 = ax.w1 * ay.w0;
                    float w10 = ax.w0 * ay.w1, w11 = ax.w1 * ay.w1;
                    float aF = fmaf(w11, v11.x, fmaf(w10, v10.x, fmaf(w01, v01.x, w00 * v00.x)));
                    float aB = fmaf(w11, v11.y, fmaf(w10, v10.y, fmaf(w01, v01.y, w00 * v00.y)));
                    xv0 = wk0 * aF + (1.0f - wk0) * aB;
                }
                if (az.ok) {
                    // planes 1 & 2 share this branch: issue all 8 tap loads first
                    float2 p1v00 = __half22float2(pb1[(az.i0 * 256 + ax.i0) * 32]);
                    float2 p1v01 = __half22float2(pb1[(az.i0 * 256 + ax.i1) * 32]);
                    float2 p1v10 = __half22float2(pb1[(az.i1 * 256 + ax.i0) * 32]);
                    float2 p1v11 = __half22float2(pb1[(az.i1 * 256 + ax.i1) * 32]);
                    float2 p2v00 = __half22float2(pb2[(ax.i0 * 256 + az.i0) * 32]);
                    float2 p2v01 = __half22float2(pb2[(ax.i0 * 256 + az.i1) * 32]);
                    float2 p2v10 = __half22float2(pb2[(ax.i1 * 256 + az.i0) * 32]);
                    float2 p2v11 = __half22float2(pb2[(ax.i1 * 256 + az.i1) * 32]);
                    {   // plane 1: (ax, az)
                        float w00 = ax.w0 * az.w0, w01 = ax.w1 * az.w0;
                        float w10 = ax.w0 * az.w1, w11 = ax.w1 * az.w1;
                        float aF = fmaf(w11, p1v11.x, fmaf(w10, p1v10.x, fmaf(w01, p1v01.x, w00 * p1v00.x)));
                        float aB = fmaf(w11, p1v11.y, fmaf(w10, p1v10.y, fmaf(w01, p1v01.y, w00 * p1v00.y)));
                        xv1 = wk1 * aF + (1.0f - wk1) * aB;
                    }
                    {   // plane 2: (az, ax)
                        float w00 = az.w0 * ax.w0, w01 = az.w1 * ax.w0;
                        float w10 = az.w0 * ax.w1, w11 = az.w1 * ax.w1;
                        float aF = fmaf(w11, p2v11.x, fmaf(w10, p2v10.x, fmaf(w01, p2v01.x, w00 * p2v00.x)));
                        float aB = fmaf(w11, p2v11.y, fmaf(w10, p2v10.y, fmaf(w01, p2v01.y, w00 * p2v00.y)));
                        xv2 = wk2 * aF + (1.0f - wk2) * aB;
                    }
                }
            }
            xh[s * 104 + lane]      = __float2half(xv0);
            xh[s * 104 + 32 + lane] = __float2half(xv1);
            xh[s * 104 + 64 + lane] = __float2half(xv2);
        }
        __syncwarp();

        // ---- layer1: [16x96] @ [96x64], fp16 mma, n split in halves ----
#pragma unroll
        for (int hn = 0; hn < 2; hn++) {
            float d1[4][4];
#pragma unroll
            for (int nt2 = 0; nt2 < 4; nt2++) {
                int nt = hn * 4 + nt2;
                float bl = b1s[nt * 8 + 2 * tq], bh = b1s[nt * 8 + 2 * tq + 1];
                d1[nt2][0] = bl; d1[nt2][1] = bh; d1[nt2][2] = bl; d1[nt2][3] = bh;
            }
#pragma unroll
            for (int kt = 0; kt < 6; kt++) {
                uint32_t a0, a1, a2, a3;
                ldsm_x4(a0, a1, a2, a3, a_x + kt * 32);
#pragma unroll
                for (int nt2 = 0; nt2 < 4; nt2++) {
                    int nt = hn * 4 + nt2;
                    uint32_t bv0, bv1;
                    ldsm_x2(bv0, bv1, b_w1 + nt * 1664 + kt * 32);
                    mma_f16(d1[nt2][0], d1[nt2][1], d1[nt2][2], d1[nt2][3], a0, a1, a2, a3, bv0, bv1);
                }
            }
            int gq = lane >> 2;
#pragma unroll
            for (int nt2 = 0; nt2 < 4; nt2++) {
                int nt = hn * 4 + nt2;
                *(__half2*)(hh + gq * 72 + nt * 8 + 2 * tq) =
                    __floats2half2_rn(softplus_fast(d1[nt2][0]), softplus_fast(d1[nt2][1]));
                *(__half2*)(hh + (gq + 8) * 72 + nt * 8 + 2 * tq) =
                    __floats2half2_rn(softplus_fast(d1[nt2][2]), softplus_fast(d1[nt2][3]));
            }
        }
        __syncwarp();

        // ---- layer2: [16x64] @ [64x40] ----
        float d2[5][4];
#pragma unroll
        for (int nt = 0; nt < 5; nt++) {
            float bl = b2s[nt * 8 + 2 * tq], bh = b2s[nt * 8 + 2 * tq + 1];
            d2[nt][0] = bl; d2[nt][1] = bh; d2[nt][2] = bl; d2[nt][3] = bh;
        }
#pragma unroll
        for (int kt = 0; kt < 4; kt++) {
            uint32_t a0, a1, a2, a3;
            ldsm_x4(a0, a1, a2, a3, a_h + kt * 32);
#pragma unroll
            for (int nt = 0; nt < 5; nt++) {
                uint32_t bv0, bv1;
                ldsm_x2(bv0, bv1, b_w2 + nt * 1152 + kt * 32);
                mma_f16(d2[nt][0], d2[nt][1], d2[nt][2], d2[nt][3], a0, a1, a2, a3, bv0, bv1);
            }
        }
        __syncwarp();
        {
            int gq = lane >> 2;
#pragma unroll
            for (int nt = 0; nt < 5; nt++) {
                *(float2*)(outf + gq * 44 + nt * 8 + 2 * tq)       = make_float2(d2[nt][0], d2[nt][1]);
                *(float2*)(outf + (gq + 8) * 44 + nt * 8 + 2 * tq) = make_float2(d2[nt][2], d2[nt][3]);
            }
        }
        __syncwarp();

#pragma unroll 4
        for (int s = 0; s < 16; s++) {
            float v = outf[s * 44 + 1 + lane];
            cols[(size_t)(smp0 + s) * 32 + lane] = sigmoid_fast(v) * 1.002f - 0.001f;
        }
        if (lane < 16) sigs[smp0 + lane] = outf[lane * 44];
        __syncwarp();

        g = gnext;
    }
}

// ---------------- kernel 3: fused coarse weights + importance sampling, warp per ray ----------------
#define KF_W 8
__global__ void __launch_bounds__(KF_W*32) k_fine() {
    __shared__ float zsh[KF_W][49];
    __shared__ float ssh[KF_W][49];
    __shared__ float wsh[KF_W][48];
    __shared__ float zmsh[KF_W][48];
    __shared__ float cdfsh[KF_W][47];
    __shared__ float bmn[KF_W], bmx[KF_W];
    if (blockIdx.x == 0 && threadIdx.x == 0) g_ctr1 = MODEL_WARPS;
    int lane = threadIdx.x & 31, wrp = threadIdx.x >> 5;
    int ray = blockIdx.x * KF_W + wrp;
    float* z   = zsh[wrp];
    float* sg  = ssh[wrp];
    float* w   = wsh[wrp];
    float* zm  = zmsh[wrp];
    float* cdf = cdfsh[wrp];

    for (int i = lane; i < 48; i += 32) {
        z[i]  = g_depth_c[ray * 48 + i];
        sg[i] = g_sig_c[ray * 48 + i];
    }
    __syncwarp();

    float a0, t0, a1 = 0.0f, t1 = 1.0f;
    {
        int i = lane;
        float dens = softplusf(0.5f * (sg[i] + sg[i + 1]) - 1.0f);
        a0 = 1.0f - expf(-dens * (z[i + 1] - z[i]));
        t0 = 1.0f - a0 + 1e-10f;
        zm[i] = 0.5f * (z[i] + z[i + 1]);
    }
    if (lane < 15) {
        int i = 32 + lane;
        float dens = softplusf(0.5f * (sg[i] + sg[i + 1]) - 1.0f);
        a1 = 1.0f - expf(-dens * (z[i + 1] - z[i]));
        t1 = 1.0f - a1 + 1e-10f;
        zm[i] = 0.5f * (z[i] + z[i + 1]);
    }
    float p0 = t0;
#pragma unroll
    for (int off = 1; off < 32; off <<= 1) {
        float v = __shfl_up_sync(0xffffffffu, p0, off);
        if (lane >= off) p0 *= v;
    }
    float tot0 = __shfl_sync(0xffffffffu, p0, 31);
    float p0prev = __shfl_up_sync(0xffffffffu, p0, 1);
    float P0 = (lane == 0) ? 1.0f : p0prev;
    float p1 = t1;
#pragma unroll
    for (int off = 1; off < 32; off <<= 1) {
        float v = __shfl_up_sync(0xffffffffu, p1, off);
        if (lane >= off) p1 *= v;
    }
    float p1prev = __shfl_up_sync(0xffffffffu, p1, 1);
    float P1 = tot0 * ((lane == 0) ? 1.0f : p1prev);

    w[lane] = a0 * P0;
    if (lane < 15) w[32 + lane] = a1 * P1;
    __syncwarp();

    if (lane == 0) { bmn[wrp] = z[0]; bmx[wrp] = z[47]; }
    __syncthreads();
    if (threadIdx.x == 0) {
        float mn = bmn[0], mx = bmx[0];
#pragma unroll
        for (int i = 1; i < KF_W; i++) { mn = fminf(mn, bmn[i]); mx = fmaxf(mx, bmx[i]); }
        atomicMin(&g_dmin_bits, __float_as_int(mn));
        atomicMax(&g_dmax_bits, __float_as_int(mx));
    }

    float s0 = 0.0f, s1 = 0.0f;
    {
        int j = lane;
        if (j < 45)
            s0 = 0.5f * (fmaxf(w[j], w[j + 1]) + fmaxf(w[j + 1], w[j + 2])) + 0.01f + 1e-5f;
    }
    if (lane < 13) {
        int j = 32 + lane;
        s1 = 0.5f * (fmaxf(w[j], w[j + 1]) + fmaxf(w[j + 1], w[j + 2])) + 0.01f + 1e-5f;
    }
    float q0 = s0;
#pragma unroll
    for (int off = 1; off < 32; off <<= 1) {
        float v = __shfl_up_sync(0xffffffffu, q0, off);
        if (lane >= off) q0 += v;
    }
    float tot0s = __shfl_sync(0xffffffffu, q0, 31);
    float q1 = s1;
#pragma unroll
    for (int off = 1; off < 32; off <<= 1) {
        float v = __shfl_up_sync(0xffffffffu, q1, off);
        if (lane >= off) q1 += v;
    }
    float sum = tot0s + __shfl_sync(0xffffffffu, q1, 31);
    if (lane == 0) cdf[0] = 0.0f;
    if (lane < 45) cdf[lane + 1] = q0 / sum;
    if (lane < 13) cdf[33 + lane] = (tot0s + q1) / sum;
    __syncwarp();

    uint32_t ka, kb; derive_key(1u, ka, kb);
#pragma unroll
    for (int half = 0; half < 2; half++) {
        int j = half * 32 + lane;
        if (j < 48) {
            float u = tf_uniform(ka, kb, (uint32_t)(ray * 48 + j));
            int pos = 0;
#pragma unroll
            for (int step = 32; step; step >>= 1) {
                int np = pos + step;
                if (np <= 46 && cdf[np - 1] <= u) pos = np;
            }
            int ind = pos;
            int below = ind - 1; if (below < 0) below = 0;
            int above = ind;     if (above > 45) above = 45;
            float c0 = cdf[below], c1 = cdf[above];
            float b0 = zm[below],  b1v = zm[above];
            float denom = c1 - c0;
            if (denom < 1e-5f) denom = 1.0f;
            g_depth_f[ray * 48 + j] = b0 + (u - c0) / denom * (b1v - b0);
        }
    }
}

// ---------------- kernel 4: unify + final march, warp per ray, parallel scan ----------------
#define KL_W 8
__global__ void __launch_bounds__(KL_W*32) k_final(
    const float* __restrict__ ro, const float* __restrict__ rd,
    float* __restrict__ out)
{
    __shared__ __align__(16) float sd[KL_W][96];
    __shared__ __align__(16) float ssg[KL_W][96];
    __shared__ __align__(16) float wbuf[KL_W][96];
    __shared__ __align__(16) int   sidx[KL_W][96];
    int lane = threadIdx.x & 31, wrp = threadIdx.x >> 5;
    int ray = blockIdx.x * KL_W + wrp;

    for (int i = lane; i < 48; i += 32) {
        sd[wrp][i]       = g_depth_c[ray * 48 + i];
        sd[wrp][48 + i]  = g_depth_f[ray * 48 + i];
        ssg[wrp][i]      = g_sig_c[ray * 48 + i];
        ssg[wrp][48 + i] = g_sig_f[ray * 48 + i];
    }
    __syncwarp();
#pragma unroll
    for (int t = 0; t < 3; t++) {
        int e = lane + t * 32;
        float de = sd[wrp][e];
        int rank = 0;
        for (int j = 0; j < 96; j++) {
            float dj = sd[wrp][j];
            rank += (dj < de || (dj == de && j < e)) ? 1 : 0;
        }
        sidx[wrp][rank] = e;
    }
    __syncwarp();

    float av[3], tv[3], dm[3];
#pragma unroll
    for (int c = 0; c < 3; c++) {
        int k = c * 32 + lane;
        av[c] = 0.0f; tv[c] = 1.0f; dm[c] = 0.0f;
        if (k < 95) {
            int i0 = sidx[wrp][k], i1 = sidx[wrp][k + 1];
            float d0 = sd[wrp][i0], d1 = sd[wrp][i1];
            float s0 = ssg[wrp][i0], s1 = ssg[wrp][i1];
            float dens = softplus_fast(0.5f * (s0 + s1) - 1.0f);
            float alpha = 1.0f - __expf(-dens * (d1 - d0));
            av[c] = alpha;
            tv[c] = 1.0f - alpha + 1e-10f;
            dm[c] = 0.5f * (d0 + d1);
        }
    }
    float carry = 1.0f;
    float accW = 0.0f, accWD = 0.0f;
#pragma unroll
    for (int c = 0; c < 3; c++) {
        float p = tv[c];
#pragma unroll
        for (int off = 1; off < 32; off <<= 1) {
            float v = __shfl_up_sync(0xffffffffu, p, off);
            if (lane >= off) p *= v;
        }
        float pprev = __shfl_up_sync(0xffffffffu, p, 1);
        float P = carry * ((lane == 0) ? 1.0f : pprev);
        float wk = av[c] * P;
        int k = c * 32 + lane;
        wbuf[wrp][k] = (k < 95) ? wk : 0.0f;
        if (k < 95) { accW += wk; accWD += wk * dm[c]; }
        carry *= __shfl_sync(0xffffffffu, p, 31);
    }
    if (lane == 31) wbuf[wrp][95] = 0.0f;
#pragma unroll
    for (int off = 16; off; off >>= 1) {
        accW  += __shfl_xor_sync(0xffffffffu, accW, off);
        accWD += __shfl_xor_sync(0xffffffffu, accWD, off);
    }
    __syncwarp();

    const float* colc = g_col_c + (size_t)ray * 48 * 32 + lane;
    const float* colf = g_col_f + (size_t)ray * 48 * 32 + lane;
    float accC = 0.0f;
#pragma unroll 8
    for (int j = 0; j < 96; j++) {
        float wj  = (j < 95) ? wbuf[wrp][j] : 0.0f;
        float wjm = (j > 0)  ? wbuf[wrp][j - 1] : 0.0f;
        float coef = 0.5f * (wj + wjm);
        int i = sidx[wrp][j];
        const float* cb = (i < 48) ? colc : colf;
        float cc = cb[(size_t)(i < 48 ? i : i - 48) * 32];
        accC = fmaf(coef, cc, accC);
    }

    out[OUT_RGB + (size_t)ray * 32 + lane] = accC * 2.0f - 1.0f;
    if (lane == 0) {
        float wt = accW;
        float dep = accWD / wt;
        if (isnan(dep)) dep = __int_as_float(0x7f800000);
        float dmin = __int_as_float(g_dmin_bits);
        float dmax = __int_as_float(g_dmax_bits);
        dep = fminf(fmaxf(dep, dmin), dmax);
        out[OUT_DEPTH + ray] = dep;
        out[OUT_WT + ray] = wt;
    }
    if (lane < 3) {
        float o_ = ro[ray * 3 + lane], d_ = rd[ray * 3 + lane];
        out[OUT_XYZ + (size_t)ray * 3 + lane] = 2.0f * (o_ * accW + d_ * accWD) - 1.0f;
    }
}

// ---------------- launcher ----------------
extern "C" void kernel_launch(void* const* d_in, const int* in_sizes, int n_in,
                              void* d_out, int out_size) {
    const float* front  = (const float*)d_in[0];
    const float* back   = (const float*)d_in[1];
    const float* ro     = (const float*)d_in[2];
    const float* rd     = (const float*)d_in[3];
    const float* weight = (const float*)d_in[4];
    const float* w1     = (const float*)d_in[5];
    const float* b1     = (const float*)d_in[6];
    const float* w2     = (const float*)d_in[7];
    const float* b2     = (const float*)d_in[8];
    float* out = (float*)d_out;

    cudaFuncSetAttribute(k_model, cudaFuncAttributeMaxDynamicSharedMemorySize, SM_TOTAL_BYTES);

    k_transpose<<<dim3(8, 256, 6), dim3(32, 8)>>>(front, back);
    k_model<<<MODEL_BLOCKS, 512, SM_TOTAL_BYTES>>>(ro, rd, weight, w1, b1, w2, b2, 0);
    k_fine<<<NRAY / KF_W, KF_W * 32>>>();
    k_model<<<MODEL_BLOCKS, 512, SM_TOTAL_BYTES>>>(ro, rd, weight, w1, b1, w2, b2, 1);
    k_final<<<NRAY / KL_W, KL_W * 32>>>(ro, rd, out);
    (void)in_sizes; (void)n_in; (void)out_size;
}

// round 17
// speedup vs baseline: 1.1185x; 1.0742x over previous
#include <cuda_runtime.h>
#include <cuda_fp16.h>
#include <cstdint>
#include <math.h>

// ---------------- problem constants ----------------
#define Bb 2
#define Rr 4096
#define Ss 48
#define NRAY   (Bb*Rr)        // 8192
#define NSAMP  (NRAY*Ss)      // 393216
#define NG16   (NSAMP/16)     // 24576

#define RAY_START 2.25f
#define STEPF 0.0223404255319148936f  // (3.3-2.25)/47

#define OUT_RGB   0
#define OUT_DEPTH 262144
#define OUT_WT    270336
#define OUT_XYZ   278528

#define MODEL_BLOCKS 296
#define MODEL_WARPS  (MODEL_BLOCKS*16)   // 4736

// ---------------- scratch ----------------
__device__ __half g_planes_h[(size_t)Bb*3*256*256*64];
__device__ float g_depth_c[NSAMP];
__device__ float g_depth_f[NSAMP];
__device__ float g_col_c[(size_t)NSAMP*32];
__device__ float g_col_f[(size_t)NSAMP*32];
__device__ float g_sig_c[NSAMP];
__device__ float g_sig_f[NSAMP];
__device__ int   g_dmin_bits;
__device__ int   g_dmax_bits;
__device__ unsigned int g_ctr0;
__device__ unsigned int g_ctr1;

// ---------------- math helpers ----------------
__device__ __forceinline__ float softplusf(float x) {
    return fmaxf(x, 0.0f) + log1pf(expf(-fabsf(x)));
}
__device__ __forceinline__ float softplus_fast(float x) {
    return fmaxf(x, 0.0f) + __logf(1.0f + __expf(-fabsf(x)));
}
__device__ __forceinline__ float sigmoid_fast(float x) {
    return __fdividef(1.0f, 1.0f + __expf(-x));
}

__device__ __forceinline__ uint32_t smaddr(const void* p) {
    return (uint32_t)__cvta_generic_to_shared(p);
}
__device__ __forceinline__ void ldsm_x4(uint32_t& r0, uint32_t& r1, uint32_t& r2, uint32_t& r3, uint32_t a) {
    asm volatile("ldmatrix.sync.aligned.m8n8.x4.shared.b16 {%0,%1,%2,%3}, [%4];"
                 : "=r"(r0), "=r"(r1), "=r"(r2), "=r"(r3) : "r"(a));
}
__device__ __forceinline__ void ldsm_x2(uint32_t& r0, uint32_t& r1, uint32_t a) {
    asm volatile("ldmatrix.sync.aligned.m8n8.x2.shared.b16 {%0,%1}, [%2];"
                 : "=r"(r0), "=r"(r1) : "r"(a));
}
__device__ __forceinline__ void mma_f16(float& d0, float& d1, float& d2, float& d3,
                                        uint32_t a0, uint32_t a1, uint32_t a2, uint32_t a3,
                                        uint32_t b0, uint32_t b1) {
    asm volatile(
        "mma.sync.aligned.m16n8k16.row.col.f32.f16.f16.f32 "
        "{%0,%1,%2,%3}, {%4,%5,%6,%7}, {%8,%9}, {%0,%1,%2,%3};"
        : "+f"(d0), "+f"(d1), "+f"(d2), "+f"(d3)
        : "r"(a0), "r"(a1), "r"(a2), "r"(a3), "r"(b0), "r"(b1));
}

// ---------------- Threefry-2x32 (JAX, partitionable variant) ----------------
__device__ __forceinline__ uint32_t rotl32(uint32_t x, int r) {
    return (x << r) | (x >> (32 - r));
}
__device__ __forceinline__ void tf2x32(uint32_t k0, uint32_t k1,
                                       uint32_t x0, uint32_t x1,
                                       uint32_t& o0, uint32_t& o1) {
    uint32_t ks2 = k0 ^ k1 ^ 0x1BD11BDAu;
    x0 += k0; x1 += k1;
#define TFR(r) { x0 += x1; x1 = rotl32(x1, r); x1 ^= x0; }
    TFR(13) TFR(15) TFR(26) TFR(6)  x0 += k1;  x1 += ks2 + 1u;
    TFR(17) TFR(29) TFR(16) TFR(24) x0 += ks2; x1 += k0 + 2u;
    TFR(13) TFR(15) TFR(26) TFR(6)  x0 += k0;  x1 += k1 + 3u;
    TFR(17) TFR(29) TFR(16) TFR(24) x0 += k1;  x1 += ks2 + 4u;
    TFR(13) TFR(15) TFR(26) TFR(6)  x0 += ks2; x1 += k0 + 5u;
#undef TFR
    o0 = x0; o1 = x1;
}
__device__ __forceinline__ void derive_key(uint32_t idx, uint32_t& ka, uint32_t& kb) {
    tf2x32(0u, 42u, 0u, idx, ka, kb);
}
__device__ __forceinline__ float tf_uniform(uint32_t ka, uint32_t kb, uint32_t i) {
    uint32_t o0, o1;
    tf2x32(ka, kb, 0u, i, o0, o1);
    uint32_t bits = o0 ^ o1;
    float f = __uint_as_float((bits >> 9) | 0x3f800000u) - 1.0f;
    return fmaxf(f, 0.0f);
}

// ---------------- kernel 1: transpose planes to channel-last fp16 (+ init scalars) ----------------
__global__ void k_transpose(const float* __restrict__ front, const float* __restrict__ back) {
    __shared__ float tf[32][33];
    __shared__ float tb[32][33];
    if (blockIdx.x == 0 && blockIdx.y == 0 && blockIdx.z == 0 &&
        threadIdx.x == 0 && threadIdx.y == 0) {
        g_dmin_bits = 0x7f800000;
        g_dmax_bits = 0x00000000;
        g_ctr0 = MODEL_WARPS;
    }
    int bp = blockIdx.z;
    int y  = blockIdx.y;
    int x0 = blockIdx.x * 32;
    int tx = threadIdx.x, ty = threadIdx.y;
    __half2* out = (__half2*)g_planes_h;
#pragma unroll
    for (int i = 0; i < 4; i++) {
        int c = ty + i * 8;
        size_t src = ((size_t)(bp * 32 + c) * 65536) + (size_t)y * 256 + x0 + tx;
        tf[c][tx] = front[src];
        tb[c][tx] = back[src];
    }
    __syncthreads();
#pragma unroll
    for (int i = 0; i < 4; i++) {
        int xx = ty + i * 8;
        out[(((size_t)bp * 65536) + (size_t)y * 256 + x0 + xx) * 32 + tx] =
            __floats2half2_rn(tf[tx][xx], tb[tx][xx]);
    }
}

// ---------------- kernel 2: model, warp per 16-sample group, fp16 mma MLP ----------------
// smem float-offsets (16 warps):
//   w1h 0..3328, w2h 3328..4768, b1s 4768, b2s 4832, wsig 4872
//   xb  4968..18280  (16 x 1664 halves)
//   hb  18280..27496 (16 x 1152 halves)
//   csts 27496..27529 (33 floats)
#define SM_W1H  0
#define SM_W2H  3328
#define SM_B1   4768
#define SM_B2   4832
#define SM_WSIG 4872
#define SM_XB   4968
#define SM_HB   18280
#define SM_CONST 27496
#define SM_TOTAL_BYTES (27532*4)

extern __shared__ __align__(16) float smem[];

struct Axis { float w0, w1; int i0, i1; bool ok; };
__device__ __forceinline__ Axis axis_prep(float g) {
    Axis a;
    float x = (g + 1.0f) * 128.0f - 0.5f;
    float x0f = floorf(x);
    int x0 = (int)x0f;
    float w = x - x0f;
    bool v0 = (x0 >= 0) & (x0 < 256);
    bool v1 = (x0 >= -1) & (x0 < 255);
    a.w0 = v0 ? 1.0f - w : 0.0f;
    a.w1 = v1 ? w : 0.0f;
    a.i0 = min(max(x0, 0), 255);
    a.i1 = min(max(x0 + 1, 0), 255);
    a.ok = (x0 >= -1) & (x0 <= 255);
    return a;
}

__global__ void __launch_bounds__(512, 2) k_model(
    const float* __restrict__ ro, const float* __restrict__ rd,
    const float* __restrict__ weight,
    const float* __restrict__ w1, const float* __restrict__ b1,
    const float* __restrict__ w2, const float* __restrict__ b2,
    int fine_pass)
{
    __half* w1h = (__half*)(smem + SM_W1H);
    __half* w2h = (__half*)(smem + SM_W2H);
    float* b1s  = smem + SM_B1;
    float* b2s  = smem + SM_B2;
    float* wsig = smem + SM_WSIG;
    float* csts = smem + SM_CONST;   // [0..31] cols const, [32] sigma const

    int tid = threadIdx.x;
    for (int i = tid; i < 96 * 64; i += 512) {
        int k = i >> 6, n = i & 63;
        w1h[n * 104 + k] = __float2half(w1[i]);
    }
    for (int i = tid; i < 64 * 40; i += 512) {
        int k = i / 40, n = i % 40;
        w2h[n * 72 + k] = (n < 33) ? __float2half(w2[k * 33 + n]) : __half(0.0f);
    }
    if (tid < 64) b1s[tid] = b1[tid];
    if (tid < 40) b2s[tid] = (tid < 33) ? b2[tid] : 0.0f;
    if (tid < 96) wsig[tid] = 1.0f / (1.0f + expf(-weight[tid]));
    __syncthreads();

    float* cols = fine_pass ? g_col_f : g_col_c;
    float* sigs = fine_pass ? g_sig_f : g_sig_c;
    unsigned int* ctr = fine_pass ? &g_ctr1 : &g_ctr0;

    int lane = tid & 31, wrp = tid >> 5;
    int tq = lane & 3;
    __half* xh = (__half*)(smem + SM_XB) + wrp * 1664;   // [16][104]
    __half* hh = (__half*)(smem + SM_HB) + wrp * 1152;   // [16][72]
    float*  outf = (float*)xh;                           // reuse as [16][44] float

    uint32_t a_x = smaddr(xh) + (((lane & 15) * 104 + ((lane >> 4) * 8)) * 2);
    uint32_t a_h = smaddr(hh) + (((lane & 15) * 72  + ((lane >> 4) * 8)) * 2);
    uint32_t b_w1 = smaddr(w1h) + (((lane & 7) * 104 + (((lane >> 3) & 1) * 8)) * 2);
    uint32_t b_w2 = smaddr(w2h) + (((lane & 7) * 72  + (((lane >> 3) & 1) * 8)) * 2);

    float wk0 = wsig[lane], wk1 = wsig[32 + lane], wk2 = wsig[64 + lane];

    // ---- warp 0: compute zero-input MLP constants via the EXACT mma path ----
    if (wrp == 0) {
#pragma unroll
        for (int s = 0; s < 16; s++) {
            xh[s * 104 + lane]      = __half(0.0f);
            xh[s * 104 + 32 + lane] = __half(0.0f);
            xh[s * 104 + 64 + lane] = __half(0.0f);
        }
        __syncwarp();
#pragma unroll
        for (int hn = 0; hn < 2; hn++) {
            float d1[4][4];
#pragma unroll
            for (int nt2 = 0; nt2 < 4; nt2++) {
                int nt = hn * 4 + nt2;
                float bl = b1s[nt * 8 + 2 * tq], bh = b1s[nt * 8 + 2 * tq + 1];
                d1[nt2][0] = bl; d1[nt2][1] = bh; d1[nt2][2] = bl; d1[nt2][3] = bh;
            }
#pragma unroll
            for (int kt = 0; kt < 6; kt++) {
                uint32_t a0, a1, a2, a3;
                ldsm_x4(a0, a1, a2, a3, a_x + kt * 32);
#pragma unroll
                for (int nt2 = 0; nt2 < 4; nt2++) {
                    int nt = hn * 4 + nt2;
                    uint32_t bv0, bv1;
                    ldsm_x2(bv0, bv1, b_w1 + nt * 1664 + kt * 32);
                    mma_f16(d1[nt2][0], d1[nt2][1], d1[nt2][2], d1[nt2][3], a0, a1, a2, a3, bv0, bv1);
                }
            }
            int gq = lane >> 2;
#pragma unroll
            for (int nt2 = 0; nt2 < 4; nt2++) {
                int nt = hn * 4 + nt2;
                *(__half2*)(hh + gq * 72 + nt * 8 + 2 * tq) =
                    __floats2half2_rn(softplus_fast(d1[nt2][0]), softplus_fast(d1[nt2][1]));
                *(__half2*)(hh + (gq + 8) * 72 + nt * 8 + 2 * tq) =
                    __floats2half2_rn(softplus_fast(d1[nt2][2]), softplus_fast(d1[nt2][3]));
            }
        }
        __syncwarp();
        float d2[5][4];
#pragma unroll
        for (int nt = 0; nt < 5; nt++) {
            float bl = b2s[nt * 8 + 2 * tq], bh = b2s[nt * 8 + 2 * tq + 1];
            d2[nt][0] = bl; d2[nt][1] = bh; d2[nt][2] = bl; d2[nt][3] = bh;
        }
#pragma unroll
        for (int kt = 0; kt < 4; kt++) {
            uint32_t a0, a1, a2, a3;
            ldsm_x4(a0, a1, a2, a3, a_h + kt * 32);
#pragma unroll
            for (int nt = 0; nt < 5; nt++) {
                uint32_t bv0, bv1;
                ldsm_x2(bv0, bv1, b_w2 + nt * 1152 + kt * 32);
                mma_f16(d2[nt][0], d2[nt][1], d2[nt][2], d2[nt][3], a0, a1, a2, a3, bv0, bv1);
            }
        }
        __syncwarp();
        {
            int gq = lane >> 2;
#pragma unroll
            for (int nt = 0; nt < 5; nt++) {
                *(float2*)(outf + gq * 44 + nt * 8 + 2 * tq)       = make_float2(d2[nt][0], d2[nt][1]);
                *(float2*)(outf + (gq + 8) * 44 + nt * 8 + 2 * tq) = make_float2(d2[nt][2], d2[nt][3]);
            }
        }
        __syncwarp();
        csts[lane] = sigmoid_fast(outf[1 + lane]) * 1.002f - 0.001f;   // sample 0 row
        if (lane == 0) csts[32] = outf[0];
    }
    __syncthreads();

    float cconst = csts[lane];
    float sconst = csts[32];

    uint32_t ka0, kb0; derive_key(0u, ka0, kb0);

    int g = blockIdx.x * 16 + wrp;

    while (g < NG16) {
        int smp0 = g * 16;
        int ray = g / 3;
        int b = ray >> 12;
        float ox = 2.0f * ro[ray * 3 + 0], oy = 2.0f * ro[ray * 3 + 1], oz = 2.0f * ro[ray * 3 + 2];
        float dx = 2.0f * rd[ray * 3 + 0], dy = 2.0f * rd[ray * 3 + 1], dz = 2.0f * rd[ray * 3 + 2];
        const __half2* pb0 = (const __half2*)g_planes_h + (size_t)b * 3 * 65536 * 32 + (size_t)lane;
        const __half2* pb1 = pb0 + (size_t)65536 * 32;
        const __half2* pb2 = pb1 + (size_t)65536 * 32;

        int sidx = smp0 + (lane & 15);
        float dval;
        if (!fine_pass) {
            int sloc = (g % 3) * 16 + (lane & 15);
            float u = tf_uniform(ka0, kb0, (uint32_t)sidx);
            float d0 = RAY_START + (float)sloc * STEPF;
            dval = d0 + u * STEPF;
            if (lane < 16) g_depth_c[sidx] = dval;
        } else {
            dval = g_depth_f[sidx];
        }

        int gnext;
        if (lane == 0) gnext = (int)atomicAdd(ctr, 1u);
        gnext = __shfl_sync(0xffffffffu, gnext, 0);

        // ---- group-level zero test: lane evaluates its own sample ----
        {
            float cxo = fmaf(dval, dx, ox);
            float cyo = fmaf(dval, dy, oy);
            float czo = fmaf(dval, dz, oz);
            Axis axo = axis_prep(cxo);
            Axis ayo = axis_prep(cyo);
            Axis azo = axis_prep(czo);
            bool nz = axo.ok && (ayo.ok || azo.ok);
            if (__ballot_sync(0xffffffffu, nz) == 0u) {
                // all 16 samples produce zero features -> constant MLP output
#pragma unroll 4
                for (int s = 0; s < 16; s++)
                    cols[(size_t)(smp0 + s) * 32 + lane] = cconst;
                if (lane < 16) sigs[smp0 + lane] = sconst;
                g = gnext;
                continue;
            }
        }

        // ---- phase A: gather 16 samples, lane = channel; OOB skips (warp-uniform) ----
#pragma unroll 4
        for (int s = 0; s < 16; s++) {
            float d = __shfl_sync(0xffffffffu, dval, s);
            float cx = fmaf(d, dx, ox);
            float cy = fmaf(d, dy, oy);
            float cz = fmaf(d, dz, oz);
            float xv0 = 0.0f, xv1 = 0.0f, xv2 = 0.0f;
            Axis ax = axis_prep(cx);
            if (ax.ok) {
                Axis ay = axis_prep(cy);
                Axis az = axis_prep(cz);
                if (ay.ok) {   // plane 0: (ax, ay)
                    float2 v00 = __half22float2(pb0[(ay.i0 * 256 + ax.i0) * 32]);
                    float2 v01 = __half22float2(pb0[(ay.i0 * 256 + ax.i1) * 32]);
                    float2 v10 = __half22float2(pb0[(ay.i1 * 256 + ax.i0) * 32]);
                    float2 v11 = __half22float2(pb0[(ay.i1 * 256 + ax.i1) * 32]);
                    float w00 = ax.w0 * ay.w0, w01 = ax.w1 * ay.w0;
                    float w10 = ax.w0 * ay.w1, w11 = ax.w1 * ay.w1;
                    float aF = fmaf(w11, v11.x, fmaf(w10, v10.x, fmaf(w01, v01.x, w00 * v00.x)));
                    float aB = fmaf(w11, v11.y, fmaf(w10, v10.y, fmaf(w01, v01.y, w00 * v00.y)));
                    xv0 = wk0 * aF + (1.0f - wk0) * aB;
                }
                if (az.ok) {
                    float2 p1v00 = __half22float2(pb1[(az.i0 * 256 + ax.i0) * 32]);
                    float2 p1v01 = __half22float2(pb1[(az.i0 * 256 + ax.i1) * 32]);
                    float2 p1v10 = __half22float2(pb1[(az.i1 * 256 + ax.i0) * 32]);
                    float2 p1v11 = __half22float2(pb1[(az.i1 * 256 + ax.i1) * 32]);
                    float2 p2v00 = __half22float2(pb2[(ax.i0 * 256 + az.i0) * 32]);
                    float2 p2v01 = __half22float2(pb2[(ax.i0 * 256 + az.i1) * 32]);
                    float2 p2v10 = __half22float2(pb2[(ax.i1 * 256 + az.i0) * 32]);
                    float2 p2v11 = __half22float2(pb2[(ax.i1 * 256 + az.i1) * 32]);
                    {   // plane 1: (ax, az)
                        float w00 = ax.w0 * az.w0, w01 = ax.w1 * az.w0;
                        float w10 = ax.w0 * az.w1, w11 = ax.w1 * az.w1;
                        float aF = fmaf(w11, p1v11.x, fmaf(w10, p1v10.x, fmaf(w01, p1v01.x, w00 * p1v00.x)));
                        float aB = fmaf(w11, p1v11.y, fmaf(w10, p1v10.y, fmaf(w01, p1v01.y, w00 * p1v00.y)));
                        xv1 = wk1 * aF + (1.0f - wk1) * aB;
                    }
                    {   // plane 2: (az, ax)
                        float w00 = az.w0 * ax.w0, w01 = az.w1 * ax.w0;
                        float w10 = az.w0 * ax.w1, w11 = az.w1 * ax.w1;
                        float aF = fmaf(w11, p2v11.x, fmaf(w10, p2v10.x, fmaf(w01, p2v01.x, w00 * p2v00.x)));
                        float aB = fmaf(w11, p2v11.y, fmaf(w10, p2v10.y, fmaf(w01, p2v01.y, w00 * p2v00.y)));
                        xv2 = wk2 * aF + (1.0f - wk2) * aB;
                    }
                }
            }
            xh[s * 104 + lane]      = __float2half(xv0);
            xh[s * 104 + 32 + lane] = __float2half(xv1);
            xh[s * 104 + 64 + lane] = __float2half(xv2);
        }
        __syncwarp();

        // ---- layer1: [16x96] @ [96x64], fp16 mma, n split in halves ----
#pragma unroll
        for (int hn = 0; hn < 2; hn++) {
            float d1[4][4];
#pragma unroll
            for (int nt2 = 0; nt2 < 4; nt2++) {
                int nt = hn * 4 + nt2;
                float bl = b1s[nt * 8 + 2 * tq], bh = b1s[nt * 8 + 2 * tq + 1];
                d1[nt2][0] = bl; d1[nt2][1] = bh; d1[nt2][2] = bl; d1[nt2][3] = bh;
            }
#pragma unroll
            for (int kt = 0; kt < 6; kt++) {
                uint32_t a0, a1, a2, a3;
                ldsm_x4(a0, a1, a2, a3, a_x + kt * 32);
#pragma unroll
                for (int nt2 = 0; nt2 < 4; nt2++) {
                    int nt = hn * 4 + nt2;
                    uint32_t bv0, bv1;
                    ldsm_x2(bv0, bv1, b_w1 + nt * 1664 + kt * 32);
                    mma_f16(d1[nt2][0], d1[nt2][1], d1[nt2][2], d1[nt2][3], a0, a1, a2, a3, bv0, bv1);
                }
            }
            int gq = lane >> 2;
#pragma unroll
            for (int nt2 = 0; nt2 < 4; nt2++) {
                int nt = hn * 4 + nt2;
                *(__half2*)(hh + gq * 72 + nt * 8 + 2 * tq) =
                    __floats2half2_rn(softplus_fast(d1[nt2][0]), softplus_fast(d1[nt2][1]));
                *(__half2*)(hh + (gq + 8) * 72 + nt * 8 + 2 * tq) =
                    __floats2half2_rn(softplus_fast(d1[nt2][2]), softplus_fast(d1[nt2][3]));
            }
        }
        __syncwarp();

        // ---- layer2: [16x64] @ [64x40] ----
        float d2[5][4];
#pragma unroll
        for (int nt = 0; nt < 5; nt++) {
            float bl = b2s[nt * 8 + 2 * tq], bh = b2s[nt * 8 + 2 * tq + 1];
            d2[nt][0] = bl; d2[nt][1] = bh; d2[nt][2] = bl; d2[nt][3] = bh;
        }
#pragma unroll
        for (int kt = 0; kt < 4; kt++) {
            uint32_t a0, a1, a2, a3;
            ldsm_x4(a0, a1, a2, a3, a_h + kt * 32);
#pragma unroll
            for (int nt = 0; nt < 5; nt++) {
                uint32_t bv0, bv1;
                ldsm_x2(bv0, bv1, b_w2 + nt * 1152 + kt * 32);
                mma_f16(d2[nt][0], d2[nt][1], d2[nt][2], d2[nt][3], a0, a1, a2, a3, bv0, bv1);
            }
        }
        __syncwarp();
        {
            int gq = lane >> 2;
#pragma unroll
            for (int nt = 0; nt < 5; nt++) {
                *(float2*)(outf + gq * 44 + nt * 8 + 2 * tq)       = make_float2(d2[nt][0], d2[nt][1]);
                *(float2*)(outf + (gq + 8) * 44 + nt * 8 + 2 * tq) = make_float2(d2[nt][2], d2[nt][3]);
            }
        }
        __syncwarp();

#pragma unroll 4
        for (int s = 0; s < 16; s++) {
            float v = outf[s * 44 + 1 + lane];
            cols[(size_t)(smp0 + s) * 32 + lane] = sigmoid_fast(v) * 1.002f - 0.001f;
        }
        if (lane < 16) sigs[smp0 + lane] = outf[lane * 44];
        __syncwarp();

        g = gnext;
    }
}

// ---------------- kernel 3: fused coarse weights + importance sampling, warp per ray ----------------
#define KF_W 8
__global__ void __launch_bounds__(KF_W*32) k_fine() {
    __shared__ float zsh[KF_W][49];
    __shared__ float ssh[KF_W][49];
    __shared__ float wsh[KF_W][48];
    __shared__ float zmsh[KF_W][48];
    __shared__ float cdfsh[KF_W][47];
    __shared__ float bmn[KF_W], bmx[KF_W];
    if (blockIdx.x == 0 && threadIdx.x == 0) g_ctr1 = MODEL_WARPS;
    int lane = threadIdx.x & 31, wrp = threadIdx.x >> 5;
    int ray = blockIdx.x * KF_W + wrp;
    float* z   = zsh[wrp];
    float* sg  = ssh[wrp];
    float* w   = wsh[wrp];
    float* zm  = zmsh[wrp];
    float* cdf = cdfsh[wrp];

    for (int i = lane; i < 48; i += 32) {
        z[i]  = g_depth_c[ray * 48 + i];
        sg[i] = g_sig_c[ray * 48 + i];
    }
    __syncwarp();

    float a0, t0, a1 = 0.0f, t1 = 1.0f;
    {
        int i = lane;
        float dens = softplusf(0.5f * (sg[i] + sg[i + 1]) - 1.0f);
        a0 = 1.0f - expf(-dens * (z[i + 1] - z[i]));
        t0 = 1.0f - a0 + 1e-10f;
        zm[i] = 0.5f * (z[i] + z[i + 1]);
    }
    if (lane < 15) {
        int i = 32 + lane;
        float dens = softplusf(0.5f * (sg[i] + sg[i + 1]) - 1.0f);
        a1 = 1.0f - expf(-dens * (z[i + 1] - z[i]));
        t1 = 1.0f - a1 + 1e-10f;
        zm[i] = 0.5f * (z[i] + z[i + 1]);
    }
    float p0 = t0;
#pragma unroll
    for (int off = 1; off < 32; off <<= 1) {
        float v = __shfl_up_sync(0xffffffffu, p0, off);
        if (lane >= off) p0 *= v;
    }
    float tot0 = __shfl_sync(0xffffffffu, p0, 31);
    float p0prev = __shfl_up_sync(0xffffffffu, p0, 1);
    float P0 = (lane == 0) ? 1.0f : p0prev;
    float p1 = t1;
#pragma unroll
    for (int off = 1; off < 32; off <<= 1) {
        float v = __shfl_up_sync(0xffffffffu, p1, off);
        if (lane >= off) p1 *= v;
    }
    float p1prev = __shfl_up_sync(0xffffffffu, p1, 1);
    float P1 = tot0 * ((lane == 0) ? 1.0f : p1prev);

    w[lane] = a0 * P0;
    if (lane < 15) w[32 + lane] = a1 * P1;
    __syncwarp();

    if (lane == 0) { bmn[wrp] = z[0]; bmx[wrp] = z[47]; }
    __syncthreads();
    if (threadIdx.x == 0) {
        float mn = bmn[0], mx = bmx[0];
#pragma unroll
        for (int i = 1; i < KF_W; i++) { mn = fminf(mn, bmn[i]); mx = fmaxf(mx, bmx[i]); }
        atomicMin(&g_dmin_bits, __float_as_int(mn));
        atomicMax(&g_dmax_bits, __float_as_int(mx));
    }

    float s0 = 0.0f, s1 = 0.0f;
    {
        int j = lane;
        if (j < 45)
            s0 = 0.5f * (fmaxf(w[j], w[j + 1]) + fmaxf(w[j + 1], w[j + 2])) + 0.01f + 1e-5f;
    }
    if (lane < 13) {
        int j = 32 + lane;
        s1 = 0.5f * (fmaxf(w[j], w[j + 1]) + fmaxf(w[j + 1], w[j + 2])) + 0.01f + 1e-5f;
    }
    float q0 = s0;
#pragma unroll
    for (int off = 1; off < 32; off <<= 1) {
        float v = __shfl_up_sync(0xffffffffu, q0, off);
        if (lane >= off) q0 += v;
    }
    float tot0s = __shfl_sync(0xffffffffu, q0, 31);
    float q1 = s1;
#pragma unroll
    for (int off = 1; off < 32; off <<= 1) {
        float v = __shfl_up_sync(0xffffffffu, q1, off);
        if (lane >= off) q1 += v;
    }
    float sum = tot0s + __shfl_sync(0xffffffffu, q1, 31);
    if (lane == 0) cdf[0] = 0.0f;
    if (lane < 45) cdf[lane + 1] = q0 / sum;
    if (lane < 13) cdf[33 + lane] = (tot0s + q1) / sum;
    __syncwarp();

    uint32_t ka, kb; derive_key(1u, ka, kb);
#pragma unroll
    for (int half = 0; half < 2; half++) {
        int j = half * 32 + lane;
        if (j < 48) {
            float u = tf_uniform(ka, kb, (uint32_t)(ray * 48 + j));
            int pos = 0;
#pragma unroll
            for (int step = 32; step; step >>= 1) {
                int np = pos + step;
                if (np <= 46 && cdf[np - 1] <= u) pos = np;
            }
            int ind = pos;
            int below = ind - 1; if (below < 0) below = 0;
            int above = ind;     if (above > 45) above = 45;
            float c0 = cdf[below], c1 = cdf[above];
            float b0 = zm[below],  b1v = zm[above];
            float denom = c1 - c0;
            if (denom < 1e-5f) denom = 1.0f;
            g_depth_f[ray * 48 + j] = b0 + (u - c0) / denom * (b1v - b0);
        }
    }
}

// ---------------- kernel 4: unify + final march, warp per ray, parallel scan ----------------
#define KL_W 8
__global__ void __launch_bounds__(KL_W*32) k_final(
    const float* __restrict__ ro, const float* __restrict__ rd,
    float* __restrict__ out)
{
    __shared__ __align__(16) float sd[KL_W][96];
    __shared__ __align__(16) float ssg[KL_W][96];
    __shared__ __align__(16) float wbuf[KL_W][96];
    __shared__ __align__(16) int   sidx[KL_W][96];
    int lane = threadIdx.x & 31, wrp = threadIdx.x >> 5;
    int ray = blockIdx.x * KL_W + wrp;

    for (int i = lane; i < 48; i += 32) {
        sd[wrp][i]       = g_depth_c[ray * 48 + i];
        sd[wrp][48 + i]  = g_depth_f[ray * 48 + i];
        ssg[wrp][i]      = g_sig_c[ray * 48 + i];
        ssg[wrp][48 + i] = g_sig_f[ray * 48 + i];
    }
    __syncwarp();
#pragma unroll
    for (int t = 0; t < 3; t++) {
        int e = lane + t * 32;
        float de = sd[wrp][e];
        int rank = 0;
        for (int j = 0; j < 96; j++) {
            float dj = sd[wrp][j];
            rank += (dj < de || (dj == de && j < e)) ? 1 : 0;
        }
        sidx[wrp][rank] = e;
    }
    __syncwarp();

    float av[3], tv[3], dm[3];
#pragma unroll
    for (int c = 0; c < 3; c++) {
        int k = c * 32 + lane;
        av[c] = 0.0f; tv[c] = 1.0f; dm[c] = 0.0f;
        if (k < 95) {
            int i0 = sidx[wrp][k], i1 = sidx[wrp][k + 1];
            float d0 = sd[wrp][i0], d1 = sd[wrp][i1];
            float s0 = ssg[wrp][i0], s1 = ssg[wrp][i1];
            float dens = softplus_fast(0.5f * (s0 + s1) - 1.0f);
            float alpha = 1.0f - __expf(-dens * (d1 - d0));
            av[c] = alpha;
            tv[c] = 1.0f - alpha + 1e-10f;
            dm[c] = 0.5f * (d0 + d1);
        }
    }
    float carry = 1.0f;
    float accW = 0.0f, accWD = 0.0f;
#pragma unroll
    for (int c = 0; c < 3; c++) {
        float p = tv[c];
#pragma unroll
        for (int off = 1; off < 32; off <<= 1) {
            float v = __shfl_up_sync(0xffffffffu, p, off);
            if (lane >= off) p *= v;
        }
        float pprev = __shfl_up_sync(0xffffffffu, p, 1);
        float P = carry * ((lane == 0) ? 1.0f : pprev);
        float wk = av[c] * P;
        int k = c * 32 + lane;
        wbuf[wrp][k] = (k < 95) ? wk : 0.0f;
        if (k < 95) { accW += wk; accWD += wk * dm[c]; }
        carry *= __shfl_sync(0xffffffffu, p, 31);
    }
    if (lane == 31) wbuf[wrp][95] = 0.0f;
#pragma unroll
    for (int off = 16; off; off >>= 1) {
        accW  += __shfl_xor_sync(0xffffffffu, accW, off);
        accWD += __shfl_xor_sync(0xffffffffu, accWD, off);
    }
    __syncwarp();

    const float* colc = g_col_c + (size_t)ray * 48 * 32 + lane;
    const float* colf = g_col_f + (size_t)ray * 48 * 32 + lane;
    float accC = 0.0f;
#pragma unroll 8
    for (int j = 0; j < 96; j++) {
        float wj  = (j < 95) ? wbuf[wrp][j] : 0.0f;
        float wjm = (j > 0)  ? wbuf[wrp][j - 1] : 0.0f;
        float coef = 0.5f * (wj + wjm);
        int i = sidx[wrp][j];
        const float* cb = (i < 48) ? colc : colf;
        float cc = cb[(size_t)(i < 48 ? i : i - 48) * 32];
        accC = fmaf(coef, cc, accC);
    }

    out[OUT_RGB + (size_t)ray * 32 + lane] = accC * 2.0f - 1.0f;
    if (lane == 0) {
        float wt = accW;
        float dep = accWD / wt;
        if (isnan(dep)) dep = __int_as_float(0x7f800000);
        float dmin = __int_as_float(g_dmin_bits);
        float dmax = __int_as_float(g_dmax_bits);
        dep = fminf(fmaxf(dep, dmin), dmax);
        out[OUT_DEPTH + ray] = dep;
        out[OUT_WT + ray] = wt;
    }
    if (lane < 3) {
        float o_ = ro[ray * 3 + lane], d_ = rd[ray * 3 + lane];
        out[OUT_XYZ + (size_t)ray * 3 + lane] = 2.0f * (o_ * accW + d_ * accWD) - 1.0f;
    }
}

// ---------------- launcher ----------------
extern "C" void kernel_launch(void* const* d_in, const int* in_sizes, int n_in,
                              void* d_out, int out_size) {
    const float* front  = (const float*)d_in[0];
    const float* back   = (const float*)d_in[1];
    const float* ro     = (const float*)d_in[2];
    const float* rd     = (const float*)d_in[3];
    const float* weight = (const float*)d_in[4];
    const float* w1     = (const float*)d_in[5];
    const float* b1     = (const float*)d_in[6];
    const float* w2     = (const float*)d_in[7];
    const float* b2     = (const float*)d_in[8];
    float* out = (float*)d_out;

    cudaFuncSetAttribute(k_model, cudaFuncAttributeMaxDynamicSharedMemorySize, SM_TOTAL_BYTES);

    k_transpose<<<dim3(8, 256, 6), dim3(32, 8)>>>(front, back);
    k_model<<<MODEL_BLOCKS, 512, SM_TOTAL_BYTES>>>(ro, rd, weight, w1, b1, w2, b2, 0);
    k_fine<<<NRAY / KF_W, KF_W * 32>>>();
    k_model<<<MODEL_BLOCKS, 512, SM_TOTAL_BYTES>>>(ro, rd, weight, w1, b1, w2, b2, 1);
    k_final<<<NRAY / KL_W, KL_W * 32>>>(ro, rd, out);
    (void)in_sizes; (void)n_in; (void)out_size;
}